// round 7
// baseline (speedup 1.0000x reference)
#include <cuda_runtime.h>
#include <cuda_bf16.h>

// Inputs (metadata order):
//   d_in[0]: pre     float32  [N, 3]   (log-softmax)
//   d_in[1]: y_true  int32    [N]
//   d_in[2]: weight  float32  scalar
// Output: float32 scalar = -sum(w_i * pre[i, y_i]) / N,
//   w_i = weight if |argmax(pre_i) - y_i| == 2 else 1.
//
// Single kernel, single graph node. Blocks atomicAdd partials into a device
// accumulator; the last-finishing block (fence + counter) publishes
// out = g_acc * (-1/N) and resets the globals for graph replay.

#define NBLOCKS 2048
#define NTHREADS 256

__device__ float g_acc;                 // zero-init; reset by finishing block
__device__ unsigned int g_done_count;   // zero-init; reset by finishing block

__device__ __forceinline__ float row_term(float a, float b, float c, int yt, float w) {
    // argmax with first-occurrence tie-breaking (strict >)
    int pred = 0;
    float best = a;
    if (b > best) { best = b; pred = 1; }
    if (c > best) { pred = 2; }
    float picked = (yt == 0) ? a : ((yt == 1) ? b : c);
    int d = pred - yt;
    bool penal = (d == 2) || (d == -2);
    return penal ? (w * picked) : picked;
}

__device__ __forceinline__ float quad_term(float4 f0, float4 f1, float4 f2,
                                           int4 yv, float w) {
    float t = 0.0f;
    t += row_term(f0.x, f0.y, f0.z, yv.x, w);
    t += row_term(f0.w, f1.x, f1.y, yv.y, w);
    t += row_term(f1.z, f1.w, f2.x, yv.z, w);
    t += row_term(f2.y, f2.z, f2.w, yv.w, w);
    return t;
}

__global__ void __launch_bounds__(NTHREADS)
nll_stream_kernel(const float* __restrict__ pre,
                  const int* __restrict__ y,
                  const float* __restrict__ wp,
                  float* __restrict__ out,
                  int n, float inv_n_neg) {
    const float4* p4 = reinterpret_cast<const float4*>(pre);
    const int4*   y4 = reinterpret_cast<const int4*>(y);
    const float w = *wp;

    const int nquad  = n >> 2;
    const int tid    = blockIdx.x * blockDim.x + threadIdx.x;
    const int stride = gridDim.x * blockDim.x;

    float acc = 0.0f;

    if (nquad == 4 * stride && (n & 3) == 0) {
        // Exact-fit path: each thread owns exactly 4 quads (this problem's N).
        #pragma unroll
        for (int u = 0; u < 4; u++) {
            int q = tid + u * stride;
            float4 f0 = __ldcs(&p4[3 * q + 0]);
            float4 f1 = __ldcs(&p4[3 * q + 1]);
            float4 f2 = __ldcs(&p4[3 * q + 2]);
            int4   yv = __ldcs(&y4[q]);
            acc += quad_term(f0, f1, f2, yv, w);
        }
    } else {
        // generic fallback
        for (int q = tid; q < nquad; q += stride) {
            float4 f0 = __ldcs(&p4[3 * q + 0]);
            float4 f1 = __ldcs(&p4[3 * q + 1]);
            float4 f2 = __ldcs(&p4[3 * q + 2]);
            acc += quad_term(f0, f1, f2, __ldcs(&y4[q]), w);
        }
        for (int i = (nquad << 2) + tid; i < n; i += stride)
            acc += row_term(pre[3 * i + 0], pre[3 * i + 1], pre[3 * i + 2], y[i], w);
    }

    // intra-block reduction
    #pragma unroll
    for (int off = 16; off > 0; off >>= 1)
        acc += __shfl_down_sync(0xFFFFFFFFu, acc, off);

    __shared__ float s[NTHREADS / 32];
    int lane = threadIdx.x & 31;
    int wid  = threadIdx.x >> 5;
    if (lane == 0) s[wid] = acc;
    __syncthreads();

    if (wid == 0 && lane == 0) {
        float v = s[0];
        #pragma unroll
        for (int k = 1; k < NTHREADS / 32; k++) v += s[k];

        atomicAdd(&g_acc, v);
        __threadfence();
        unsigned int prev = atomicAdd(&g_done_count, 1u);
        if (prev == (unsigned int)(gridDim.x - 1)) {
            // all g_acc adds are visible (each block fenced before its counter add)
            out[0] = g_acc * inv_n_neg;   // = -sum / N
            g_acc = 0.0f;                 // reset for next graph replay
            g_done_count = 0u;
        }
    }
}

extern "C" void kernel_launch(void* const* d_in, const int* in_sizes, int n_in,
                              void* d_out, int out_size) {
    const float* pre = (const float*)d_in[0];
    const int*   y   = (const int*)d_in[1];
    const float* wp  = (const float*)d_in[2];
    float* out = (float*)d_out;

    const int n = in_sizes[1];   // y_true element count = number of rows

    nll_stream_kernel<<<NBLOCKS, NTHREADS>>>(pre, y, wp, out, n, -1.0f / (float)n);
}

// round 8
// speedup vs baseline: 1.0071x; 1.0071x over previous
#include <cuda_runtime.h>
#include <cuda_bf16.h>

// Inputs (metadata order):
//   d_in[0]: pre     float32  [N, 3]   (log-softmax)
//   d_in[1]: y_true  int32    [N]
//   d_in[2]: weight  float32  scalar
// Output: float32 scalar = -sum(w_i * pre[i, y_i]) / N,
//   w_i = weight if |argmax(pre_i) - y_i| == 2 else 1.
//
// Single kernel, single graph node. Per-block relaxed atomicAdd into g_acc;
// completion ordered by an acq_rel scoped atomic counter (NO __threadfence —
// gpu-scope fence emits CCTL.IVALL which flushes the SM's L1 and cost ~3us in R7).
// Final block exchanges g_acc with 0 (read+reset), publishes out, resets counter.

#define NBLOCKS 2048
#define NTHREADS 256

__device__ float g_acc;                 // zero-init; reset by publishing block
__device__ unsigned int g_done_count;   // zero-init; reset by publishing block

__device__ __forceinline__ float row_term(float a, float b, float c, int yt, float w) {
    // argmax with first-occurrence tie-breaking (strict >)
    int pred = 0;
    float best = a;
    if (b > best) { best = b; pred = 1; }
    if (c > best) { pred = 2; }
    float picked = (yt == 0) ? a : ((yt == 1) ? b : c);
    int d = pred - yt;
    bool penal = (d == 2) || (d == -2);
    return penal ? (w * picked) : picked;
}

__device__ __forceinline__ float quad_term(float4 f0, float4 f1, float4 f2,
                                           int4 yv, float w) {
    float t = 0.0f;
    t += row_term(f0.x, f0.y, f0.z, yv.x, w);
    t += row_term(f0.w, f1.x, f1.y, yv.y, w);
    t += row_term(f1.z, f1.w, f2.x, yv.z, w);
    t += row_term(f2.y, f2.z, f2.w, yv.w, w);
    return t;
}

__global__ void __launch_bounds__(NTHREADS)
nll_stream_kernel(const float* __restrict__ pre,
                  const int* __restrict__ y,
                  const float* __restrict__ wp,
                  float* __restrict__ out,
                  int n, float inv_n_neg) {
    const float4* p4 = reinterpret_cast<const float4*>(pre);
    const int4*   y4 = reinterpret_cast<const int4*>(y);
    const float w = *wp;

    const int nquad  = n >> 2;
    const int tid    = blockIdx.x * blockDim.x + threadIdx.x;
    const int stride = gridDim.x * blockDim.x;

    float acc = 0.0f;

    if (nquad == 4 * stride && (n & 3) == 0) {
        // Exact-fit path: each thread owns exactly 4 quads (this problem's N).
        #pragma unroll
        for (int u = 0; u < 4; u++) {
            int q = tid + u * stride;
            float4 f0 = __ldcs(&p4[3 * q + 0]);
            float4 f1 = __ldcs(&p4[3 * q + 1]);
            float4 f2 = __ldcs(&p4[3 * q + 2]);
            int4   yv = __ldcs(&y4[q]);
            acc += quad_term(f0, f1, f2, yv, w);
        }
    } else {
        // generic fallback
        for (int q = tid; q < nquad; q += stride) {
            float4 f0 = __ldcs(&p4[3 * q + 0]);
            float4 f1 = __ldcs(&p4[3 * q + 1]);
            float4 f2 = __ldcs(&p4[3 * q + 2]);
            acc += quad_term(f0, f1, f2, __ldcs(&y4[q]), w);
        }
        for (int i = (nquad << 2) + tid; i < n; i += stride)
            acc += row_term(pre[3 * i + 0], pre[3 * i + 1], pre[3 * i + 2], y[i], w);
    }

    // intra-block reduction
    #pragma unroll
    for (int off = 16; off > 0; off >>= 1)
        acc += __shfl_down_sync(0xFFFFFFFFu, acc, off);

    __shared__ float s[NTHREADS / 32];
    int lane = threadIdx.x & 31;
    int wid  = threadIdx.x >> 5;
    if (lane == 0) s[wid] = acc;
    __syncthreads();

    if (wid == 0 && lane == 0) {
        float v = s[0];
        #pragma unroll
        for (int k = 1; k < NTHREADS / 32; k++) v += s[k];

        atomicAdd(&g_acc, v);   // relaxed, L2-resident

        // release my g_acc add / acquire everyone else's — no L1 flush
        unsigned int prev;
        asm volatile("atom.add.acq_rel.gpu.u32 %0, [%1], %2;"
                     : "=r"(prev)
                     : "l"(&g_done_count), "r"(1u)
                     : "memory");

        if (prev == (unsigned int)(gridDim.x - 1)) {
            float total = atomicExch(&g_acc, 0.0f);  // read + reset in one L2 op
            out[0] = total * inv_n_neg;              // = -sum / N
            asm volatile("st.relaxed.gpu.u32 [%0], %1;"
                         :: "l"(&g_done_count), "r"(0u) : "memory");
        }
    }
}

extern "C" void kernel_launch(void* const* d_in, const int* in_sizes, int n_in,
                              void* d_out, int out_size) {
    const float* pre = (const float*)d_in[0];
    const int*   y   = (const int*)d_in[1];
    const float* wp  = (const float*)d_in[2];
    float* out = (float*)d_out;

    const int n = in_sizes[1];   // y_true element count = number of rows

    nll_stream_kernel<<<NBLOCKS, NTHREADS>>>(pre, y, wp, out, n, -1.0f / (float)n);
}